// round 15
// baseline (speedup 1.0000x reference)
#include <cuda_runtime.h>
#include <cuda_fp16.h>
#include <cstdint>
#include <cstddef>

// Problem constants
#define BATCH   32768
#define PP      24
#define CIN     64
#define COUT    64
#define NORB    24
#define KK      1536          // P*CIN
#define NNDIM   1536          // P*COUT
#define SLOT_BYTES 24576      // A 16KB + B 8KB
#define SMEM_DYN (3 * SLOT_BYTES)            // 72KB -> 3 CTAs/SM

// prep grid split
#define KTC_BLOCKS  (NORB * COUT)                               // 1536
#define CVT_BLOCKS  ((int)(((size_t)BATCH * KK / 8) / 256))     // 24576

// device-global scratch (no allocations allowed)
__device__ __half g_Xh[(size_t)BATCH * KK];            // x in fp16 [m][k]
__device__ __half g_KTc[(size_t)NORB * COUT * KK];     // compacted weights [i][o][kk]
__device__ int g_nt[NORB];                             // distinct orbits per i
__device__ int g_jcnt[NORB * PP];                      // j-count per (i,tt)
__device__ unsigned char g_jlist[NORB * PP * PP];      // j indices per (i,tt)

// ---------------- helpers ----------------
__device__ __forceinline__ uint32_t smem_u32(const void* p) {
    uint32_t a;
    asm("{ .reg .u64 t; cvta.to.shared.u64 t, %1; cvt.u32.u64 %0, t; }"
        : "=r"(a) : "l"(p));
    return a;
}

#define LDSM4(r, addr) \
    asm volatile("ldmatrix.sync.aligned.m8n8.x4.shared.b16 {%0,%1,%2,%3}, [%4];" \
                 : "=r"((r)[0]), "=r"((r)[1]), "=r"((r)[2]), "=r"((r)[3]) \
                 : "r"(addr))

#define MMA_F16(c, a, b0, b1) \
    asm volatile("mma.sync.aligned.m16n8k16.row.col.f32.f16.f16.f32 " \
                 "{%0,%1,%2,%3}, {%4,%5,%6,%7}, {%8,%9}, {%0,%1,%2,%3};" \
                 : "+f"((c)[0]), "+f"((c)[1]), "+f"((c)[2]), "+f"((c)[3]) \
                 : "r"((a)[0]), "r"((a)[1]), "r"((a)[2]), "r"((a)[3]), \
                   "r"(b0), "r"(b1))

#define STS128(addr, v) \
    asm volatile("st.shared.v4.b32 [%0], {%1,%2,%3,%4};" \
                 :: "r"(addr), "r"((v).x), "r"((v).y), "r"((v).z), "r"((v).w))

#define LDS128(v, addr) \
    asm volatile("ld.shared.v4.b32 {%0,%1,%2,%3}, [%4];" \
                 : "=r"((v).x), "=r"((v).y), "=r"((v).z), "=r"((v).w) : "r"(addr))

#define CPASYNC16(dst, src) \
    asm volatile("cp.async.cg.shared.global [%0], [%1], 16;" :: "r"(dst), "l"(src))

__device__ __forceinline__ uint4 hadd2x4(uint4 a, uint4 b) {
    uint4 r;
    *(__half2*)&r.x = __hadd2(*(__half2*)&a.x, *(__half2*)&b.x);
    *(__half2*)&r.y = __hadd2(*(__half2*)&a.y, *(__half2*)&b.y);
    *(__half2*)&r.z = __hadd2(*(__half2*)&a.z, *(__half2*)&b.z);
    *(__half2*)&r.w = __hadd2(*(__half2*)&a.w, *(__half2*)&b.w);
    return r;
}

// ---------------- kernel 1: prep (unchanged from R14) ----------------
__global__ __launch_bounds__(256) void prep(const float* __restrict__ w,
                                            const void* __restrict__ po,
                                            const float* __restrict__ x) {
    if (blockIdx.x >= KTC_BLOCKS) {
        size_t idx = (size_t)(blockIdx.x - KTC_BLOCKS) * 256 + threadIdx.x;
        const float4 f0 = *reinterpret_cast<const float4*>(x + idx * 8);
        const float4 f1 = *reinterpret_cast<const float4*>(x + idx * 8 + 4);
        __half2 h[4];
        h[0] = __floats2half2_rn(f0.x, f0.y);
        h[1] = __floats2half2_rn(f0.z, f0.w);
        h[2] = __floats2half2_rn(f1.x, f1.y);
        h[3] = __floats2half2_rn(f1.z, f1.w);
        *reinterpret_cast<uint4*>(&g_Xh[idx * 8]) = *reinterpret_cast<uint4*>(h);
        return;
    }
    const int i = blockIdx.x >> 6, o = blockIdx.x & 63;
    __shared__ int is64_sh, nt_sh;
    __shared__ int tl_sh[PP];
    {   // pair_orbit dtype detect: int64 values<24 -> all odd 32-bit words zero
        const uint32_t* pr = (const uint32_t*)po;
        if (threadIdx.x == 0) is64_sh = 1;
        __syncthreads();
        int t = threadIdx.x;
        if (t < 288 && pr[2 * t + 1] != 0u) atomicAnd(&is64_sh, 0);
        __syncthreads();
    }
    if (threadIdx.x == 0) {
        const int is64 = is64_sh;
        int nt = 0, tl[PP];
        uint32_t jm[PP];
        for (int j = 0; j < PP; j++) {
            int t = is64 ? (int)((const long long*)po)[i * PP + j]
                         : ((const int*)po)[i * PP + j];
            t = (t < 0) ? 0 : (t >= NORB ? NORB - 1 : t);
            int idx = -1;
            for (int q = 0; q < nt; q++) if (tl[q] == t) idx = q;
            if (idx < 0) { tl[nt] = t; jm[nt] = 0u; idx = nt++; }
            jm[idx] |= 1u << j;
        }
        nt_sh = nt;
        for (int q = 0; q < nt; q++) tl_sh[q] = tl[q];
        if (o == 0) {
            g_nt[i] = nt;
            for (int tt = 0; tt < nt; tt++) {
                uint32_t m = jm[tt];
                g_jcnt[i * PP + tt] = __popc(m);
                int c = 0;
                while (m) {
                    int j = __ffs(m) - 1; m &= m - 1;
                    g_jlist[(i * PP + tt) * PP + c++] = (unsigned char)j;
                }
            }
        }
    }
    __syncthreads();
    const int nt = nt_sh;
    for (int kk = threadIdx.x; kk < nt * 64; kk += 256) {
        int tt = kk >> 6, c = kk & 63;
        float v = w[o * (CIN * NORB) + c * NORB + tl_sh[tt]];
        g_KTc[(size_t)(i * COUT + o) * KK + kk] = __float2half_rn(v);
    }
}

// ---------------- kernel 2: orbit-deduped GEMM, cp.async slab streaming -------
// CTA 256 thr (8 warps, 4m x 2n), tile 128(m) x 64(o), 3 CTAs/SM.
// Stage tt: A tile = x slab j0 (cp.async direct); extras patched in smem.
__global__ __launch_bounds__(256, 3)
void gemm_f16(const float* __restrict__ bias, float* __restrict__ out) {
    extern __shared__ char smem[];
    __shared__ float bias_sh[64];
    __shared__ int s_jcnt[PP];
    __shared__ unsigned char s_jlist[PP * PP];

    const int tid = threadIdx.x;
    const int wid = tid >> 5, lid = tid & 31;
    const int i = blockIdx.x;                 // 0..23
    const int m_base = blockIdx.y * 128;

    const uint32_t sb = smem_u32(smem);
    if (tid < 64) bias_sh[tid] = bias[tid];
    const int nt = g_nt[i];
    if (tid < PP) s_jcnt[tid] = g_jcnt[i * PP + tid];
    for (int q = tid; q < PP * PP; q += 256)
        s_jlist[q] = g_jlist[i * PP * PP + q];

    // per-thread copy geometry: chunk it -> row = (tid>>3)+32*it, ch = tid&7
    // (row&7 invariant across it, so swizzled offset = adst0 + it*4096)
    const int row8 = tid >> 3, ch = tid & 7;
    const uint32_t adst0 = (uint32_t)(row8 * 128) + (uint32_t)((ch ^ (row8 & 7)) << 4);
    const __half* xsrc0 = g_Xh + (size_t)(m_base + row8) * KK + ch * 8;
    const __half* bsrc0 = g_KTc + (size_t)(i * COUT + row8) * KK + ch * 8;

    // warp layout: 4(m) x 2(n), warp tile 32x32
    const int wm = (wid & 3) * 32;
    const int wn = (wid >> 2) * 32;
    const int l15 = lid & 15;
    const int lhalf = lid >> 4;
    uint32_t aoff[2]; int ars[2];
#pragma unroll
    for (int mi = 0; mi < 2; mi++) {
        int ar = wm + mi * 16 + l15;
        aoff[mi] = (uint32_t)(ar * 128);
        ars[mi] = ar & 7;
    }
    uint32_t boff[2]; int brs[2];
#pragma unroll
    for (int p = 0; p < 2; p++) {
        int br = wn + p * 16 + l15;
        boff[p] = (uint32_t)(br * 128);
        brs[p] = br & 7;
    }

    float acc[2][4][4];
#pragma unroll
    for (int mi = 0; mi < 2; mi++)
#pragma unroll
        for (int ni = 0; ni < 4; ni++)
#pragma unroll
            for (int q = 0; q < 4; q++) acc[mi][ni][q] = 0.0f;

    __syncthreads();   // jcnt/jlist visible

    // stage copy: A slab j0 (4 chunks) + B slab (2 chunks), one commit group
    auto issue_copy = [&](int tt, int slot) {
        const uint32_t base = sb + (uint32_t)slot * SLOT_BYTES;
        const int j0 = s_jlist[tt * PP];
        const __half* xs = xsrc0 + j0 * 64;
#pragma unroll
        for (int it = 0; it < 4; it++)
            CPASYNC16(base + adst0 + (uint32_t)(it * 4096), xs + (size_t)it * 32 * KK);
        const __half* bs = bsrc0 + tt * 64;
#pragma unroll
        for (int it = 0; it < 2; it++)
            CPASYNC16(base + 16384u + adst0 + (uint32_t)(it * 4096),
                      bs + (size_t)it * 32 * KK);
        asm volatile("cp.async.commit_group;" ::: "memory");
    };

    issue_copy(0, 0);
    if (nt > 1) issue_copy(1, 1);

    int slot = 0;
    for (int tt = 0; tt < nt; tt++) {
        if (tt + 1 < nt) {
            asm volatile("cp.async.wait_group 1;" ::: "memory");
        } else {
            asm volatile("cp.async.wait_group 0;" ::: "memory");
        }
        __syncthreads();        // slab tt landed for all threads; MMA(tt-1) reads done
        if (tt + 2 < nt) {
            int ns = slot + 2; if (ns >= 3) ns -= 3;
            issue_copy(tt + 2, ns);
        }
        const uint32_t baseA = sb + (uint32_t)slot * SLOT_BYTES;
        const uint32_t baseB = baseA + 16384u;
        const int cnt = s_jcnt[tt];
        if (cnt > 1) {          // patch extras into the landed slab
            uint4 cur[4];
#pragma unroll
            for (int it = 0; it < 4; it++)
                LDS128(cur[it], baseA + adst0 + (uint32_t)(it * 4096));
            for (int q = 1; q < cnt; q++) {
                const int j = s_jlist[tt * PP + q];
                const __half* xs = xsrc0 + j * 64;
#pragma unroll
                for (int it = 0; it < 4; it++) {
                    uint4 v = *reinterpret_cast<const uint4*>(xs + (size_t)it * 32 * KK);
                    cur[it] = hadd2x4(cur[it], v);
                }
            }
#pragma unroll
            for (int it = 0; it < 4; it++)
                STS128(baseA + adst0 + (uint32_t)(it * 4096), cur[it]);
            __syncthreads();
        }
        // MMA over 4 k16 steps
#pragma unroll
        for (int ks = 0; ks < 4; ks++) {
            uint32_t a[2][4], b[2][4];
            const int chk = ks * 2 + lhalf;
#pragma unroll
            for (int mi = 0; mi < 2; mi++)
                LDSM4(a[mi], baseA + aoff[mi] + (uint32_t)((chk ^ ars[mi]) << 4));
#pragma unroll
            for (int p = 0; p < 2; p++)
                LDSM4(b[p], baseB + boff[p] + (uint32_t)((chk ^ brs[p]) << 4));
#pragma unroll
            for (int mi = 0; mi < 2; mi++) {
#pragma unroll
                for (int ni = 0; ni < 4; ni++) {
                    const int p = ni >> 1, t = ni & 1;
                    MMA_F16(acc[mi][ni], a[mi], b[p][t], b[p][t + 2]);
                }
            }
        }
        if (++slot == 3) slot = 0;
    }

    // epilogue: out cols = i*64 + o
    const int r4 = lid >> 2;
    const int c2 = (lid & 3) * 2;
    float* obase = out + (size_t)m_base * NNDIM + i * 64;
#pragma unroll
    for (int mi = 0; mi < 2; mi++) {
#pragma unroll
        for (int ni = 0; ni < 4; ni++) {
            const int row = wm + mi * 16 + r4;
            const int col = wn + ni * 8 + c2;
            const float bx = bias_sh[col];
            const float by = bias_sh[col + 1];
            float2 w0, w1;
            w0.x = acc[mi][ni][0] + bx;
            w0.y = acc[mi][ni][1] + by;
            w1.x = acc[mi][ni][2] + bx;
            w1.y = acc[mi][ni][3] + by;
            *reinterpret_cast<float2*>(obase + (size_t)row * NNDIM + col) = w0;
            *reinterpret_cast<float2*>(obase + (size_t)(row + 8) * NNDIM + col) = w1;
        }
    }
}

// ---------------- launch ----------------
extern "C" void kernel_launch(void* const* d_in, const int* in_sizes, int n_in,
                              void* d_out, int out_size) {
    const float* x = nullptr;
    const float* w = nullptr;
    const float* bias = nullptr;
    const void* po = nullptr;
    for (int t = 0; t < n_in; t++) {
        switch (in_sizes[t]) {
            case BATCH * PP * CIN:   x    = (const float*)d_in[t]; break;
            case COUT * CIN * NORB:  w    = (const float*)d_in[t]; break;
            case COUT:               bias = (const float*)d_in[t]; break;
            case PP * PP:            po   = d_in[t];               break;
            default: break;
        }
    }
    float* out = (float*)d_out;

    prep<<<KTC_BLOCKS + CVT_BLOCKS, 256>>>(w, po, x);

    cudaFuncSetAttribute(gemm_f16, cudaFuncAttributeMaxDynamicSharedMemorySize, SMEM_DYN);
    gemm_f16<<<dim3(NORB, BATCH / 128), 256, SMEM_DYN>>>(bias, out);
}

// round 17
// speedup vs baseline: 1.1579x; 1.1579x over previous
#include <cuda_runtime.h>
#include <cuda_fp16.h>
#include <cstdint>
#include <cstddef>

// Problem constants
#define BATCH   32768
#define PP      24
#define CIN     64
#define COUT    64
#define NORB    24
#define KK      1536          // P*CIN  (GEMM K)
#define NNDIM   1536          // P*COUT (GEMM N)
#define BK      64            // halfs per k-tile (128 B rows)
#define NKT     (KK / BK)     // 24
#define A_BYTES 16384         // 128 rows x 128B
#define B_BYTES 16384         // 128 rows x 128B
#define STAGE_BYTES (A_BYTES + B_BYTES)      // 32KB
#define SMEM_DYN (2 * STAGE_BYTES)           // 64KB -> 3 CTAs/SM

// grid split for merged prep kernel
#define KT_BLOCKS   ((NNDIM * KK / 8) / 256)                    // 1152
#define CVT_BLOCKS  ((int)(((size_t)BATCH * KK / 8) / 256))     // 24576

// fp16 operands (device-global scratch; no allocations allowed)
__device__ __half g_Xh[(size_t)BATCH * KK];          // x in fp16 [m][k]
__device__ __half g_KTh[(size_t)NNDIM * KK];         // gathered kernel [n][k]

// ---------------- helpers ----------------
__device__ __forceinline__ uint32_t smem_u32(const void* p) {
    uint32_t a;
    asm("{ .reg .u64 t; cvta.to.shared.u64 t, %1; cvt.u32.u64 %0, t; }"
        : "=r"(a) : "l"(p));
    return a;
}

#define LDSM4(r, addr) \
    asm volatile("ldmatrix.sync.aligned.m8n8.x4.shared.b16 {%0,%1,%2,%3}, [%4];" \
                 : "=r"((r)[0]), "=r"((r)[1]), "=r"((r)[2]), "=r"((r)[3]) \
                 : "r"(addr))

#define MMA_F16(c, a, b0, b1) \
    asm volatile("mma.sync.aligned.m16n8k16.row.col.f32.f16.f16.f32 " \
                 "{%0,%1,%2,%3}, {%4,%5,%6,%7}, {%8,%9}, {%0,%1,%2,%3};" \
                 : "+f"((c)[0]), "+f"((c)[1]), "+f"((c)[2]), "+f"((c)[3]) \
                 : "r"((a)[0]), "r"((a)[1]), "r"((a)[2]), "r"((a)[3]), \
                   "r"(b0), "r"(b1))

#define CPASYNC16(dst, src) \
    asm volatile("cp.async.cg.shared.global [%0], [%1], 16;" :: "r"(dst), "l"(src))

// ---------------- kernel 1: merged prep (KT gather + x convert) ----------------
__global__ __launch_bounds__(256) void prep(const float* __restrict__ w,
                                            const void* __restrict__ po,
                                            const float* __restrict__ x) {
    if (blockIdx.x >= KT_BLOCKS) {
        // ---- convert x -> fp16 ----
        size_t idx = (size_t)(blockIdx.x - KT_BLOCKS) * 256 + threadIdx.x;
        const float4 f0 = *reinterpret_cast<const float4*>(x + idx * 8);
        const float4 f1 = *reinterpret_cast<const float4*>(x + idx * 8 + 4);
        __half2 h[4];
        h[0] = __floats2half2_rn(f0.x, f0.y);
        h[1] = __floats2half2_rn(f0.z, f0.w);
        h[2] = __floats2half2_rn(f1.x, f1.y);
        h[3] = __floats2half2_rn(f1.z, f1.w);
        *reinterpret_cast<uint4*>(&g_Xh[idx * 8]) = *reinterpret_cast<uint4*>(h);
        return;
    }
    // ---- gather KT (pair_orbit dtype detect: int64 values<24 -> odd words 0)
    __shared__ int is64_sh;
    {
        const uint32_t* pr = (const uint32_t*)po;
        if (threadIdx.x == 0) is64_sh = 1;
        __syncthreads();
        int t = threadIdx.x;
        if (t < 288 && pr[2 * t + 1] != 0u) atomicAnd(&is64_sh, 0);
        __syncthreads();
    }
    const int is64 = is64_sh;

    int idx = blockIdx.x * 256 + threadIdx.x;          // 0 .. NN*KK/8-1
    int n = idx / (KK / 8);
    int k0 = (idx - n * (KK / 8)) * 8;
    int i = n >> 6, o = n & 63;
    int j = k0 >> 6;
    int c0 = k0 & 63;
    int orb;
    if (is64) orb = (int)((const long long*)po)[i * PP + j];
    else      orb = ((const int*)po)[i * PP + j];
    orb = (orb < 0) ? 0 : (orb >= NORB ? NORB - 1 : orb);
    const float* wp = w + o * (CIN * NORB) + c0 * NORB + orb;
    __half2 h[4];
#pragma unroll
    for (int q = 0; q < 4; q++)
        h[q] = __floats2half2_rn(wp[(2 * q) * NORB], wp[(2 * q + 1) * NORB]);
    *reinterpret_cast<uint4*>(&g_KTh[(size_t)n * KK + k0]) =
        *reinterpret_cast<uint4*>(h);
}

// ---------------- kernel 2: fp16 mma.sync GEMM (f32 acc) -----------------------
// CTA = 128 threads (4 warps, 2m x 2n), tile 128x128, warp tile 64x64,
// 2-stage cp.async pipeline, 3 CTAs/SM (3 warps/SMSP).
__global__ __launch_bounds__(128, 3)
void gemm_f16(const float* __restrict__ bias, float* __restrict__ out) {
    extern __shared__ char smem[];
    __shared__ float bias_sh[64];

    const int tid = threadIdx.x;
    const int wid = tid >> 5, lid = tid & 31;
    const int n_base = blockIdx.x * 128;
    const int m_base = blockIdx.y * 128;

    const uint32_t sb = smem_u32(smem);
    if (tid < 64) bias_sh[tid] = bias[tid];

    // loader geometry (128 threads): idx = tid + it*128, row = idx>>3 steps by 16
    // -> row&7 invariant across it, swizzled offset = adst0 + it*2048
    const int row8 = tid >> 3, ch8 = tid & 7;
    const uint32_t adst0 = (uint32_t)(row8 * 128) + (uint32_t)((ch8 ^ (row8 & 7)) << 4);
    const __half* xsrc0 = g_Xh + (size_t)(m_base + row8) * KK + ch8 * 8;
    const __half* bsrc0 = g_KTh + (size_t)(n_base + row8) * KK + ch8 * 8;

    // warp layout: 2(m) x 2(n); warp tile 64 x 64
    const int wm = (wid & 1) * 64;
    const int wn = (wid >> 1) * 64;
    const int l15 = lid & 15;
    const int lhalf = lid >> 4;

    uint32_t aoff[4]; int ars[4];
#pragma unroll
    for (int mi = 0; mi < 4; mi++) {
        int ar = wm + mi * 16 + l15;
        aoff[mi] = (uint32_t)(ar * 128);
        ars[mi] = ar & 7;
    }
    uint32_t boff[4]; int brs[4];
#pragma unroll
    for (int p = 0; p < 4; p++) {
        int br = wn + p * 16 + l15;
        boff[p] = (uint32_t)(br * 128);
        brs[p] = br & 7;
    }

    float acc[4][8][4];
#pragma unroll
    for (int mi = 0; mi < 4; mi++)
#pragma unroll
        for (int ni = 0; ni < 8; ni++)
#pragma unroll
            for (int q = 0; q < 4; q++) acc[mi][ni][q] = 0.0f;

    // stage copy: A (8 chunks/thread) + B (8 chunks/thread), one commit group
    auto issue_stage = [&](int kt, int slot) {
        const uint32_t base = sb + (uint32_t)slot * STAGE_BYTES;
        const __half* xs = xsrc0 + kt * BK;
        const __half* bs = bsrc0 + kt * BK;
#pragma unroll
        for (int it = 0; it < 8; it++)
            CPASYNC16(base + adst0 + (uint32_t)(it * 2048), xs + (size_t)it * 16 * KK);
#pragma unroll
        for (int it = 0; it < 8; it++)
            CPASYNC16(base + (uint32_t)A_BYTES + adst0 + (uint32_t)(it * 2048),
                      bs + (size_t)it * 16 * KK);
        asm volatile("cp.async.commit_group;" ::: "memory");
    };

    issue_stage(0, 0);
    issue_stage(1, 1);

    for (int kt = 0; kt < NKT; kt++) {
        if (kt == NKT - 1) {
            asm volatile("cp.async.wait_group 0;" ::: "memory");
        } else {
            asm volatile("cp.async.wait_group 1;" ::: "memory");
        }
        __syncthreads();
        {
            const uint32_t baseA = sb + (uint32_t)(kt & 1) * STAGE_BYTES;
            const uint32_t baseB = baseA + (uint32_t)A_BYTES;
#pragma unroll
            for (int ks = 0; ks < 4; ks++) {          // 4 x k16 per BK=64
                uint32_t a[4][4], b[4][4];
                const int ch = ks * 2 + lhalf;        // 16B chunk within row
#pragma unroll
                for (int p = 0; p < 4; p++)
                    LDSM4(b[p], baseB + boff[p] + (uint32_t)((ch ^ brs[p]) << 4));
#pragma unroll
                for (int mi = 0; mi < 4; mi++)
                    LDSM4(a[mi], baseA + aoff[mi] + (uint32_t)((ch ^ ars[mi]) << 4));
#pragma unroll
                for (int mi = 0; mi < 4; mi++) {
#pragma unroll
                    for (int ni = 0; ni < 8; ni++) {
                        const int p = ni >> 1, t = ni & 1;
                        MMA_F16(acc[mi][ni], a[mi], b[p][t], b[p][t + 2]);
                    }
                }
            }
        }
        __syncthreads();                 // all reads of slot (kt&1) complete
        if (kt + 2 < NKT) issue_stage(kt + 2, kt & 1);
    }

    // epilogue: coalesced float2 stores + bias
    const int r4 = lid >> 2;
    const int c2 = (lid & 3) * 2;
    float* obase = out + (size_t)m_base * NNDIM + n_base;
#pragma unroll
    for (int mi = 0; mi < 4; mi++) {
#pragma unroll
        for (int ni = 0; ni < 8; ni++) {
            const int row = wm + mi * 16 + r4;
            const int col = wn + ni * 8 + c2;
            const float bx = bias_sh[col & 63];
            const float by = bias_sh[(col + 1) & 63];
            float2 v0, v1;
            v0.x = acc[mi][ni][0] + bx;
            v0.y = acc[mi][ni][1] + by;
            v1.x = acc[mi][ni][2] + bx;
            v1.y = acc[mi][ni][3] + by;
            *reinterpret_cast<float2*>(obase + (size_t)row * NNDIM + col) = v0;
            *reinterpret_cast<float2*>(obase + (size_t)(row + 8) * NNDIM + col) = v1;
        }
    }
}

// ---------------- launch ----------------
extern "C" void kernel_launch(void* const* d_in, const int* in_sizes, int n_in,
                              void* d_out, int out_size) {
    const float* x = nullptr;
    const float* w = nullptr;
    const float* bias = nullptr;
    const void* po = nullptr;
    for (int t = 0; t < n_in; t++) {
        switch (in_sizes[t]) {
            case BATCH * PP * CIN:   x    = (const float*)d_in[t]; break;
            case COUT * CIN * NORB:  w    = (const float*)d_in[t]; break;
            case COUT:               bias = (const float*)d_in[t]; break;
            case PP * PP:            po   = d_in[t];               break;
            default: break;
        }
    }
    float* out = (float*)d_out;

    prep<<<KT_BLOCKS + CVT_BLOCKS, 256>>>(w, po, x);

    cudaFuncSetAttribute(gemm_f16, cudaFuncAttributeMaxDynamicSharedMemorySize, SMEM_DYN);
    gemm_f16<<<dim3(NNDIM / 128, BATCH / 128), 128, SMEM_DYN>>>(bias, out);
}